// round 12
// baseline (speedup 1.0000x reference)
#include <cuda_runtime.h>
#include <cuda_bf16.h>
#include <math.h>

#define NG 2048
#define IMW 128
#define IMH 128
#define FX 400.0f
#define FY 400.0f
#define CX 64.0f
#define CY 64.0f
#define NBLOCKS 128        // block b owns tiles b and 255-b (mirror pairing)
#define NTHREADS 1024
#define L2E 1.4426950408889634f
#define CAP 1536           // smem record capacity per tile (overflow -> global)

// depth-sorted per-gaussian record (3 float4), exp2-folded conic:
//  [0]ux [1]uy [2]h0 [3]h1 | [4]h2 [5]alpha [6]r [7]g | [8]b [9..11]pad
__device__ float4 g_sorted[NG * 3];
__device__ float4 g_sbbox[NG];         // depth-sorted: ux, uy, wx, wy

__device__ unsigned bar_cnt = 0;
__device__ volatile unsigned bar_gen = 0;

__device__ __forceinline__ void grid_barrier()
{
    __syncthreads();
    if (threadIdx.x == 0) {
        unsigned gen = bar_gen;
        __threadfence();
        unsigned arrived = atomicAdd(&bar_cnt, 1u);
        if (arrived == gridDim.x - 1) {
            bar_cnt = 0;
            __threadfence();
            bar_gen = gen + 1;
        } else {
            while (bar_gen == gen) __nanosleep(32);
            __threadfence();
        }
    }
    __syncthreads();
}

__constant__ float kSH_C0 = 0.28209479177387814f;
__constant__ float kSH_C1 = 0.4886025119029199f;

// dynamic smem layout (post-barrier):
//  rec  : float[2][CAP*12]  (147456 B) sorted records staged per tile
//  sidx : int[2][NG]        (16384 B)  binned sorted-stream indices
//  part : float4[16][64]    (16384 B)  segment partials
// pre-barrier aliases (block-local, dead before rec/part are written):
//  sd   : float[NG]  (8 KB, aliases rec)   all-gaussian depths
//  srec : float[16*12] (768 B, after sd)   this block's 16 records
//  sbb  : float4[16]   (256 B, after srec) this block's 16 bboxes
#define OFF_REC  0
#define OFF_SIDX (2*CAP*12*4)
#define OFF_PART (OFF_SIDX + 2*NG*4)
#define SMEM_DYN (OFF_PART + 16*64*16)

__global__ void __launch_bounds__(NTHREADS, 1) fused_kernel(
    const float* __restrict__ pws,
    const float* __restrict__ shs,
    const float* __restrict__ alphas_raw,
    const float* __restrict__ scales_raw,
    const float* __restrict__ rots_raw,
    const float* __restrict__ Rcw,
    const float* __restrict__ tcw,
    float* __restrict__ out)
{
    extern __shared__ char smem_raw[];
    float*  rec  = (float*)(smem_raw + OFF_REC);
    int*    sidx = (int*)(smem_raw + OFF_SIDX);
    float4* part = (float4*)(smem_raw + OFF_PART);
    // pre-barrier aliases
    float*  sd   = (float*)smem_raw;                 // [NG]
    float*  srec = (float*)(smem_raw + NG*4);        // [16*12]
    float4* sbb  = (float4*)(smem_raw + NG*4 + 768); // [16]

    __shared__ int wcnt[2][17];
    __shared__ int prank[32];

    const int tid = threadIdx.x;
    float* areas_out = out + 3 * IMW * IMH;

    // ---------------- Phase 0: all-gaussian depths (redundant per block) -----
    {
        float R20 = Rcw[6], R21 = Rcw[7], R22 = Rcw[8];
        float t2 = tcw[2];
        #pragma unroll
        for (int e = tid; e < NG; e += NTHREADS) {
            float x = pws[e*3+0], y = pws[e*3+1], z = pws[e*3+2];
            sd[e] = fmaf(R20, x, fmaf(R21, y, fmaf(R22, z, t2)));
        }
    }

    // ---------------- Phase 1a: preprocess 16 gaussians (threads 0..63) ------
    if (tid < 64) {
        int li = tid >> 2;                  // local gaussian 0..15
        int q  = tid & 3;
        int i  = blockIdx.x * 16 + li;

        float R00 = Rcw[0], R01 = Rcw[1], R02 = Rcw[2];
        float R10 = Rcw[3], R11 = Rcw[4], R12 = Rcw[5];
        float R20 = Rcw[6], R21 = Rcw[7], R22 = Rcw[8];
        float t0 = tcw[0], t1 = tcw[1], t2 = tcw[2];

        float pwx = pws[i*3+0], pwy = pws[i*3+1], pwz = pws[i*3+2];

        if (q < 3) {
            // color lane: channel q
            float twc0 = -(R00*t0 + R10*t1 + R20*t2);
            float twc1 = -(R01*t0 + R11*t1 + R21*t2);
            float twc2 = -(R02*t0 + R12*t1 + R22*t2);
            float dx = pwx - twc0, dy = pwy - twc1, dz = pwz - twc2;
            float dn = rsqrtf(dx*dx + dy*dy + dz*dz);
            float x = dx*dn, y = dy*dn, zd = dz*dn;

            float xx = x*x, yy = y*y, zz = zd*zd;
            float xy = x*y, yz = y*zd, xz = x*zd;

            float bs[16];
            bs[0]  = kSH_C0;
            bs[1]  = -kSH_C1 * y;
            bs[2]  =  kSH_C1 * zd;
            bs[3]  = -kSH_C1 * x;
            bs[4]  =  1.0925484305920792f  * xy;
            bs[5]  = -1.0925484305920792f  * yz;
            bs[6]  =  0.31539156525252005f * (2.0f*zz - xx - yy);
            bs[7]  = -1.0925484305920792f  * xz;
            bs[8]  =  0.5462742152960396f  * (xx - yy);
            bs[9]  = -0.5900435899266435f  * y * (3.0f*xx - yy);
            bs[10] =  2.890611442640554f   * xy * zd;
            bs[11] = -0.4570457994644658f  * y * (4.0f*zz - xx - yy);
            bs[12] =  0.3731763325901154f  * zd * (2.0f*zz - 3.0f*xx - 3.0f*yy);
            bs[13] = -0.4570457994644658f  * x * (4.0f*zz - xx - yy);
            bs[14] =  1.445305721320277f   * zd * (xx - yy);
            bs[15] = -0.5900435899266435f  * x * (xx - 3.0f*yy);

            const float* sh = shs + i*48 + q;
            float v[16];
            #pragma unroll
            for (int j = 0; j < 16; ++j) v[j] = __ldg(sh + j*3);
            float acc = 0.5f;
            #pragma unroll
            for (int j = 0; j < 16; ++j) acc = fmaf(bs[j], v[j], acc);
            srec[li*12 + 6 + q] = fmaxf(acc, 0.0f);
        } else {
            // geometry lane
            float pc0 = R00*pwx + R01*pwy + R02*pwz + t0;
            float pc1 = R10*pwx + R11*pwy + R12*pwz + t1;
            float pc2 = R20*pwx + R21*pwy + R22*pwz + t2;

            float depth = pc2;
            bool valid = depth > 0.2f;
            float z = valid ? depth : 1.0f;
            float invz = __fdividef(1.0f, z);

            float ux = FX * pc0 * invz + CX;
            float uy = FY * pc1 * invz + CY;

            float qw = rots_raw[i*4+0], qx = rots_raw[i*4+1];
            float qy = rots_raw[i*4+2], qz = rots_raw[i*4+3];
            float qn = rsqrtf(qw*qw + qx*qx + qy*qy + qz*qz);
            qw *= qn; qx *= qn; qy *= qn; qz *= qn;

            float r00 = 1.0f - 2.0f*(qy*qy + qz*qz);
            float r01 = 2.0f*(qx*qy - qw*qz);
            float r02 = 2.0f*(qx*qz + qw*qy);
            float r10 = 2.0f*(qx*qy + qw*qz);
            float r11 = 1.0f - 2.0f*(qx*qx + qz*qz);
            float r12 = 2.0f*(qy*qz - qw*qx);
            float r20 = 2.0f*(qx*qz - qw*qy);
            float r21 = 2.0f*(qy*qz + qw*qx);
            float r22 = 1.0f - 2.0f*(qx*qx + qy*qy);

            float s0 = __expf(scales_raw[i*3+0]);
            float s1 = __expf(scales_raw[i*3+1]);
            float s2 = __expf(scales_raw[i*3+2]);

            float m00 = r00*s0, m01 = r01*s1, m02 = r02*s2;
            float m10 = r10*s0, m11 = r11*s1, m12 = r12*s2;
            float m20 = r20*s0, m21 = r21*s1, m22 = r22*s2;

            float Sxx = m00*m00 + m01*m01 + m02*m02;
            float Sxy = m00*m10 + m01*m11 + m02*m12;
            float Sxz = m00*m20 + m01*m21 + m02*m22;
            float Syy = m10*m10 + m11*m11 + m12*m12;
            float Syz = m10*m20 + m11*m21 + m12*m22;
            float Szz = m20*m20 + m21*m21 + m22*m22;

            const float limx = 1.3f * 0.5f * (float)IMW / FX;
            const float limy = 1.3f * 0.5f * (float)IMH / FY;
            float txl = fminf(fmaxf(pc0 * invz, -limx), limx) * z;
            float tyl = fminf(fmaxf(pc1 * invz, -limy), limy) * z;

            float j00 = FX * invz;
            float j02 = -FX * txl * invz * invz;
            float j11 = FY * invz;
            float j12 = -FY * tyl * invz * invz;

            float T00 = j00*R00 + j02*R20;
            float T01 = j00*R01 + j02*R21;
            float T02 = j00*R02 + j02*R22;
            float T10 = j11*R10 + j12*R20;
            float T11 = j11*R11 + j12*R21;
            float T12 = j11*R12 + j12*R22;

            float u0 = T00*Sxx + T01*Sxy + T02*Sxz;
            float u1 = T00*Sxy + T01*Syy + T02*Syz;
            float u2 = T00*Sxz + T01*Syz + T02*Szz;
            float v0 = T10*Sxx + T11*Sxy + T12*Sxz;
            float v1 = T10*Sxy + T11*Syy + T12*Syz;
            float v2 = T10*Sxz + T11*Syz + T12*Szz;

            float a = u0*T00 + u1*T01 + u2*T02 + 0.3f;
            float b = u0*T10 + u1*T11 + u2*T12;
            float c = v0*T10 + v1*T11 + v2*T12 + 0.3f;

            float det = a*c - b*b;
            valid = valid && (det > 0.0f);
            float inv_det = __fdividef(1.0f, valid ? det : 1.0f);
            float ci0 = c * inv_det;
            float ci1 = -b * inv_det;
            float ci2 = a * inv_det;

            float mid = 0.5f * (a + c);
            float disc = sqrtf(fmaxf(mid*mid - det, 0.1f));
            float ar0 = 3.0f * sqrtf(fmaxf(mid + disc, 0.0f));
            float ar1 = 3.0f * sqrtf(fmaxf(mid - disc, 0.0f));
            areas_out[2*i+0] = valid ? ar0 : 0.0f;
            areas_out[2*i+1] = valid ? ar1 : 0.0f;

            float alpha = __fdividef(1.0f, 1.0f + __expf(-alphas_raw[i]));
            float alpha_eff = valid ? alpha : 0.0f;

            float wx = -1.0f, wy = -1.0f;
            if (valid && alpha_eff >= (1.0f/255.0f)) {
                float tau = 2.0f * __logf(255.0f * alpha_eff);
                if (tau > 0.0f) {
                    wx = sqrtf(tau * a) + 0.05f;
                    wy = sqrtf(tau * c) + 0.05f;
                }
            }

            srec[li*12 + 0] = ux;
            srec[li*12 + 1] = uy;
            srec[li*12 + 2] = -0.5f * L2E * ci0;   // h0
            srec[li*12 + 3] = -L2E * ci1;          // h1
            srec[li*12 + 4] = -0.5f * L2E * ci2;   // h2
            srec[li*12 + 5] = alpha_eff;
            sbb[li] = make_float4(ux, uy, wx, wy);
        }
    }
    __syncthreads();

    // ---------------- Phase 1b: global rank + scatter (2 warps/gaussian) -----
    {
        int w = tid >> 5;
        int lane = tid & 31;
        int pair = w >> 1;                       // local gaussian 0..15
        int half = w & 1;
        int i = blockIdx.x * 16 + pair;
        float d = sd[i];

        int r = 0;
        int j0 = half * 32 + lane;
        #pragma unroll 8
        for (int j = j0; j < NG; j += 64) {      // 32 iters, conflict-free
            float dj = sd[j];
            r += (dj < d) || (dj == d && j < i);
        }
        #pragma unroll
        for (int o = 16; o > 0; o >>= 1) r += __shfl_xor_sync(0xffffffffu, r, o);
        if (lane == 0) prank[w] = r;
        __syncthreads();

        if (half == 0) {
            int rt = prank[2*pair] + prank[2*pair + 1];
            if (lane < 3) {
                g_sorted[rt*3 + lane] = ((const float4*)srec)[pair*3 + lane];
            } else if (lane == 3) {
                g_sbbox[rt] = sbb[pair];
            }
        }
    }

    grid_barrier();

    // ---------------- Phase 2: binning on sorted stream — 2 mirrored tiles ---
    {
        int w = tid >> 5, lane = tid & 31;
        int h = w >> 4;                 // tile half
        int wl = w & 15;
        int tile = h ? (255 - (int)blockIdx.x) : (int)blockIdx.x;
        int tx0 = (tile & 15) * 8;
        int ty0 = (tile >> 4) * 8;
        float bx0 = (float)tx0 + 0.5f, bx1 = (float)tx0 + 7.5f;
        float by0 = (float)ty0 + 0.5f, by1 = (float)ty0 + 7.5f;

        int base0 = wl * (NG / 16);     // 128 sorted gaussians per warp
        float4 bb[4];
        unsigned mk[4];
        #pragma unroll
        for (int u = 0; u < 4; ++u) bb[u] = g_sbbox[base0 + u*32 + lane];
        int cnt = 0;
        #pragma unroll
        for (int u = 0; u < 4; ++u) {
            bool hit = (bb[u].z > 0.0f) &&
                       (bb[u].x - bb[u].z <= bx1) && (bb[u].x + bb[u].z >= bx0) &&
                       (bb[u].y - bb[u].w <= by1) && (bb[u].y + bb[u].w >= by0);
            mk[u] = __ballot_sync(0xffffffffu, hit);
            cnt += __popc(mk[u]);
        }
        if (lane == 0) wcnt[h][wl] = cnt;
        __syncthreads();
        if (tid < 2) {
            int acc = 0;
            #pragma unroll
            for (int w2 = 0; w2 < 16; ++w2) { int t = wcnt[tid][w2]; wcnt[tid][w2] = acc; acc += t; }
            wcnt[tid][16] = acc;
        }
        __syncthreads();
        int off = wcnt[h][wl];
        #pragma unroll
        for (int u = 0; u < 4; ++u) {
            if ((mk[u] >> lane) & 1u) {
                int rank = __popc(mk[u] & ((1u << lane) - 1u));
                sidx[h*NG + off + rank] = base0 + u*32 + lane;   // sorted index
            }
            off += __popc(mk[u]);
        }
        __syncthreads();
    }

    // ---------------- Phase 2.5: gather sorted records into smem -------------
    {
        const float* gp = (const float*)g_sorted;
        #pragma unroll
        for (int h2 = 0; h2 < 2; ++h2) {
            int n = min(wcnt[h2][16], CAP);
            const int* ord = sidx + h2*NG;
            float* dst = rec + h2*CAP*12;
            for (int e = tid; e < n*12; e += NTHREADS) {
                int s = e / 12, c = e - s*12;
                dst[e] = gp[ord[s]*12 + c];
            }
        }
        __syncthreads();
    }

    // ---------------- Phase 3: composite — 16 groups, no inner barriers ------
    const int grp = tid >> 6;          // 0..15
    const int h   = grp >> 3;          // tile half
    const int seg = grp & 7;
    const int pix = tid & 63;
    const int tile = h ? (255 - (int)blockIdx.x) : (int)blockIdx.x;
    const int tx0 = (tile & 15) * 8;
    const int ty0 = (tile >> 4) * 8;
    const float px = (float)(tx0 + (pix & 7)) + 0.5f;
    const float py = (float)(ty0 + (pix >> 3)) + 0.5f;

    int n = wcnt[h][16];
    int slen = (n + 7) >> 3;
    int s0 = seg * slen;
    int s1 = min(s0 + slen, n);

    float T = 1.0f;
    float cr = 0.0f, cg = 0.0f, cb = 0.0f;

    const char* rh = (const char*)(rec + h*CAP*12);
    int sm_end = min(s1, CAP);
    for (int j = s0; j < sm_end; ++j) {
        const char* p = rh + j*48;
        float4 A = *(const float4*)(p);          // ux,uy,h0,h1
        float4 B = *(const float4*)(p + 16);     // h2,alpha,r,g
        float  bc = *(const float*)(p + 32);     // b

        float dx = px - A.x;
        float dy = py - A.y;
        float t1 = fmaf(A.w, dy, A.z * dx);
        float q  = fmaf(B.x * dy, dy, dx * t1);  // power * log2(e)
        float e;
        asm("ex2.approx.f32 %0, %1;" : "=f"(e) : "f"(q));
        float g2 = fminf(B.y * e, 0.99f);
        bool ok = (q <= 0.0f) && (g2 >= (1.0f/255.0f));
        float gg = ok ? g2 : 0.0f;
        float w = T * gg;
        cr = fmaf(w, B.z, cr);
        cg = fmaf(w, B.w, cg);
        cb = fmaf(w, bc, cb);
        T -= w;

        if (((j - s0) & 7) == 7 &&
            __all_sync(0xffffffffu, T < 1e-6f)) break;
    }
    // overflow tail (only if tile had > CAP hits): exact, reads global
    if (s1 > CAP && T >= 1e-6f) {
        const int* lst = sidx + h*NG;
        const char* gp = (const char*)g_sorted;
        for (int j = max(s0, CAP); j < s1; ++j) {
            int off = lst[j] * 48;
            float4 A = __ldg((const float4*)(gp + off));
            float4 B = __ldg((const float4*)(gp + off + 16));
            float  bc = __ldg((const float*)(gp + off + 32));
            float dx = px - A.x;
            float dy = py - A.y;
            float t1 = fmaf(A.w, dy, A.z * dx);
            float q  = fmaf(B.x * dy, dy, dx * t1);
            float e;
            asm("ex2.approx.f32 %0, %1;" : "=f"(e) : "f"(q));
            float g2 = fminf(B.y * e, 0.99f);
            bool ok = (q <= 0.0f) && (g2 >= (1.0f/255.0f));
            float gg = ok ? g2 : 0.0f;
            float w = T * gg;
            cr = fmaf(w, B.z, cr);
            cg = fmaf(w, B.w, cg);
            cb = fmaf(w, bc, cb);
            T -= w;
        }
    }

    part[grp*64 + pix] = make_float4(cr, cg, cb, T);
    __syncthreads();

    if (tid < 128) {
        int hh = tid >> 6;             // tile half
        int p2 = tid & 63;
        float4 acc = part[(hh*8 + 0)*64 + p2];
        #pragma unroll
        for (int s2 = 1; s2 < 8; ++s2) {
            float4 qq = part[(hh*8 + s2)*64 + p2];
            acc.x = fmaf(acc.w, qq.x, acc.x);
            acc.y = fmaf(acc.w, qq.y, acc.y);
            acc.z = fmaf(acc.w, qq.z, acc.z);
            acc.w *= qq.w;
        }
        int tl = hh ? (255 - (int)blockIdx.x) : (int)blockIdx.x;
        int x = (tl & 15) * 8 + (p2 & 7);
        int y = (tl >> 4) * 8 + (p2 >> 3);
        out[0*(IMW*IMH) + y*IMW + x] = acc.x;
        out[1*(IMW*IMH) + y*IMW + x] = acc.y;
        out[2*(IMW*IMH) + y*IMW + x] = acc.z;
    }
}

extern "C" void kernel_launch(void* const* d_in, const int* in_sizes, int n_in,
                              void* d_out, int out_size)
{
    const float* pws        = (const float*)d_in[0];
    const float* shs        = (const float*)d_in[1];
    const float* alphas_raw = (const float*)d_in[2];
    const float* scales_raw = (const float*)d_in[3];
    const float* rots_raw   = (const float*)d_in[4];
    // d_in[5] = us (unused by the reference)
    const float* Rcw        = (const float*)d_in[6];
    const float* tcw        = (const float*)d_in[7];

    float* out = (float*)d_out;

    cudaFuncSetAttribute(fused_kernel,
                         cudaFuncAttributeMaxDynamicSharedMemorySize, SMEM_DYN);
    fused_kernel<<<NBLOCKS, NTHREADS, SMEM_DYN>>>(pws, shs, alphas_raw, scales_raw,
                                                  rots_raw, Rcw, tcw, out);
}

// round 13
// speedup vs baseline: 1.0169x; 1.0169x over previous
#include <cuda_runtime.h>
#include <cuda_bf16.h>
#include <math.h>

#define NG 2048
#define IMW 128
#define IMH 128
#define FX 400.0f
#define FY 400.0f
#define CX 64.0f
#define CY 64.0f
#define NBLOCKS 128        // block b owns tiles b and 255-b (mirror pairing)
#define NTHREADS 1024
#define L2E 1.4426950408889634f
#define CAP 1536           // smem record capacity per tile (overflow -> global)

// depth-sorted per-gaussian record (3 float4), exp2-folded conic:
//  [0]ux [1]uy [2]h0 [3]h1 | [4]h2 [5]alpha [6]r [7]g | [8]b [9..11]pad
__device__ float4 g_sorted[NG * 3];
__device__ float4 g_sbbox[NG];         // depth-sorted: ux, uy, wx, wy

// tree barrier state: 8 leaf counters (256B apart), 1 root, 1 generation flag
__device__ unsigned bar_leaf[8 * 64];  // use stride 64 uints = 256 B
__device__ unsigned bar_root = 0;
__device__ volatile unsigned bar_gen = 0;

__device__ __forceinline__ void grid_barrier_tree()
{
    __syncthreads();
    if (threadIdx.x == 0) {
        unsigned gen = bar_gen;
        __threadfence();
        // leaf: 16 blocks per counter, 8 counters in parallel
        if (atomicAdd(&bar_leaf[(blockIdx.x & 7) * 64], 1u) == 15u) {
            // root: 8 leaf-winners
            if (atomicAdd(&bar_root, 1u) == 7u) {
                #pragma unroll
                for (int k = 0; k < 8; ++k) bar_leaf[k * 64] = 0u;
                bar_root = 0u;
                __threadfence();
                bar_gen = gen + 1u;
            }
        }
        while (bar_gen == gen) __nanosleep(32);
        __threadfence();
    }
    __syncthreads();
}

__constant__ float kSH_C0 = 0.28209479177387814f;
__constant__ float kSH_C1 = 0.4886025119029199f;

// dynamic smem layout (post-barrier):
//  rec  : float[2][CAP*12]  (147456 B) sorted records staged per tile
//  sidx : int[2][NG]        (16384 B)  binned sorted-stream indices
//  part : float4[16][64]    (16384 B)  segment partials
// pre-barrier aliases (block-local, dead before rec/part are written):
//  sd   : float[NG]  (8 KB, aliases rec)   all-gaussian depths
//  srec : float[16*12] (768 B, after sd)   this block's 16 records
//  sbb  : float4[16]   (256 B, after srec) this block's 16 bboxes
#define OFF_REC  0
#define OFF_SIDX (2*CAP*12*4)
#define OFF_PART (OFF_SIDX + 2*NG*4)
#define SMEM_DYN (OFF_PART + 16*64*16)

__global__ void __launch_bounds__(NTHREADS, 1) fused_kernel(
    const float* __restrict__ pws,
    const float* __restrict__ shs,
    const float* __restrict__ alphas_raw,
    const float* __restrict__ scales_raw,
    const float* __restrict__ rots_raw,
    const float* __restrict__ Rcw,
    const float* __restrict__ tcw,
    float* __restrict__ out)
{
    extern __shared__ char smem_raw[];
    float*  rec  = (float*)(smem_raw + OFF_REC);
    int*    sidx = (int*)(smem_raw + OFF_SIDX);
    float4* part = (float4*)(smem_raw + OFF_PART);
    // pre-barrier aliases
    float*  sd   = (float*)smem_raw;                 // [NG]
    float*  srec = (float*)(smem_raw + NG*4);        // [16*12]
    float4* sbb  = (float4*)(smem_raw + NG*4 + 768); // [16]

    __shared__ int wcnt[2][17];
    __shared__ int prank[32];

    const int tid = threadIdx.x;
    float* areas_out = out + 3 * IMW * IMH;

    // ---------------- Phase 0: all-gaussian depths (redundant per block) -----
    {
        float R20 = Rcw[6], R21 = Rcw[7], R22 = Rcw[8];
        float t2 = tcw[2];
        #pragma unroll
        for (int e = tid; e < NG; e += NTHREADS) {
            float x = pws[e*3+0], y = pws[e*3+1], z = pws[e*3+2];
            sd[e] = fmaf(R20, x, fmaf(R21, y, fmaf(R22, z, t2)));
        }
    }

    // ---------------- Phase 1a: preprocess 16 gaussians (threads 0..63) ------
    if (tid < 64) {
        int li = tid >> 2;                  // local gaussian 0..15
        int q  = tid & 3;
        int i  = blockIdx.x * 16 + li;

        float R00 = Rcw[0], R01 = Rcw[1], R02 = Rcw[2];
        float R10 = Rcw[3], R11 = Rcw[4], R12 = Rcw[5];
        float R20 = Rcw[6], R21 = Rcw[7], R22 = Rcw[8];
        float t0 = tcw[0], t1 = tcw[1], t2 = tcw[2];

        float pwx = pws[i*3+0], pwy = pws[i*3+1], pwz = pws[i*3+2];

        if (q < 3) {
            // color lane: channel q
            float twc0 = -(R00*t0 + R10*t1 + R20*t2);
            float twc1 = -(R01*t0 + R11*t1 + R21*t2);
            float twc2 = -(R02*t0 + R12*t1 + R22*t2);
            float dx = pwx - twc0, dy = pwy - twc1, dz = pwz - twc2;
            float dn = rsqrtf(dx*dx + dy*dy + dz*dz);
            float x = dx*dn, y = dy*dn, zd = dz*dn;

            float xx = x*x, yy = y*y, zz = zd*zd;
            float xy = x*y, yz = y*zd, xz = x*zd;

            float bs[16];
            bs[0]  = kSH_C0;
            bs[1]  = -kSH_C1 * y;
            bs[2]  =  kSH_C1 * zd;
            bs[3]  = -kSH_C1 * x;
            bs[4]  =  1.0925484305920792f  * xy;
            bs[5]  = -1.0925484305920792f  * yz;
            bs[6]  =  0.31539156525252005f * (2.0f*zz - xx - yy);
            bs[7]  = -1.0925484305920792f  * xz;
            bs[8]  =  0.5462742152960396f  * (xx - yy);
            bs[9]  = -0.5900435899266435f  * y * (3.0f*xx - yy);
            bs[10] =  2.890611442640554f   * xy * zd;
            bs[11] = -0.4570457994644658f  * y * (4.0f*zz - xx - yy);
            bs[12] =  0.3731763325901154f  * zd * (2.0f*zz - 3.0f*xx - 3.0f*yy);
            bs[13] = -0.4570457994644658f  * x * (4.0f*zz - xx - yy);
            bs[14] =  1.445305721320277f   * zd * (xx - yy);
            bs[15] = -0.5900435899266435f  * x * (xx - 3.0f*yy);

            const float* sh = shs + i*48 + q;
            float v[16];
            #pragma unroll
            for (int j = 0; j < 16; ++j) v[j] = __ldg(sh + j*3);
            float acc = 0.5f;
            #pragma unroll
            for (int j = 0; j < 16; ++j) acc = fmaf(bs[j], v[j], acc);
            srec[li*12 + 6 + q] = fmaxf(acc, 0.0f);
        } else {
            // geometry lane
            float pc0 = R00*pwx + R01*pwy + R02*pwz + t0;
            float pc1 = R10*pwx + R11*pwy + R12*pwz + t1;
            float pc2 = R20*pwx + R21*pwy + R22*pwz + t2;

            float depth = pc2;
            bool valid = depth > 0.2f;
            float z = valid ? depth : 1.0f;
            float invz = __fdividef(1.0f, z);

            float ux = FX * pc0 * invz + CX;
            float uy = FY * pc1 * invz + CY;

            float qw = rots_raw[i*4+0], qx = rots_raw[i*4+1];
            float qy = rots_raw[i*4+2], qz = rots_raw[i*4+3];
            float qn = rsqrtf(qw*qw + qx*qx + qy*qy + qz*qz);
            qw *= qn; qx *= qn; qy *= qn; qz *= qn;

            float r00 = 1.0f - 2.0f*(qy*qy + qz*qz);
            float r01 = 2.0f*(qx*qy - qw*qz);
            float r02 = 2.0f*(qx*qz + qw*qy);
            float r10 = 2.0f*(qx*qy + qw*qz);
            float r11 = 1.0f - 2.0f*(qx*qx + qz*qz);
            float r12 = 2.0f*(qy*qz - qw*qx);
            float r20 = 2.0f*(qx*qz - qw*qy);
            float r21 = 2.0f*(qy*qz + qw*qx);
            float r22 = 1.0f - 2.0f*(qx*qx + qy*qy);

            float s0 = __expf(scales_raw[i*3+0]);
            float s1 = __expf(scales_raw[i*3+1]);
            float s2 = __expf(scales_raw[i*3+2]);

            float m00 = r00*s0, m01 = r01*s1, m02 = r02*s2;
            float m10 = r10*s0, m11 = r11*s1, m12 = r12*s2;
            float m20 = r20*s0, m21 = r21*s1, m22 = r22*s2;

            float Sxx = m00*m00 + m01*m01 + m02*m02;
            float Sxy = m00*m10 + m01*m11 + m02*m12;
            float Sxz = m00*m20 + m01*m21 + m02*m22;
            float Syy = m10*m10 + m11*m11 + m12*m12;
            float Syz = m10*m20 + m11*m21 + m12*m22;
            float Szz = m20*m20 + m21*m21 + m22*m22;

            const float limx = 1.3f * 0.5f * (float)IMW / FX;
            const float limy = 1.3f * 0.5f * (float)IMH / FY;
            float txl = fminf(fmaxf(pc0 * invz, -limx), limx) * z;
            float tyl = fminf(fmaxf(pc1 * invz, -limy), limy) * z;

            float j00 = FX * invz;
            float j02 = -FX * txl * invz * invz;
            float j11 = FY * invz;
            float j12 = -FY * tyl * invz * invz;

            float T00 = j00*R00 + j02*R20;
            float T01 = j00*R01 + j02*R21;
            float T02 = j00*R02 + j02*R22;
            float T10 = j11*R10 + j12*R20;
            float T11 = j11*R11 + j12*R21;
            float T12 = j11*R12 + j12*R22;

            float u0 = T00*Sxx + T01*Sxy + T02*Sxz;
            float u1 = T00*Sxy + T01*Syy + T02*Syz;
            float u2 = T00*Sxz + T01*Syz + T02*Szz;
            float v0 = T10*Sxx + T11*Sxy + T12*Sxz;
            float v1 = T10*Sxy + T11*Syy + T12*Syz;
            float v2 = T10*Sxz + T11*Syz + T12*Szz;

            float a = u0*T00 + u1*T01 + u2*T02 + 0.3f;
            float b = u0*T10 + u1*T11 + u2*T12;
            float c = v0*T10 + v1*T11 + v2*T12 + 0.3f;

            float det = a*c - b*b;
            valid = valid && (det > 0.0f);
            float inv_det = __fdividef(1.0f, valid ? det : 1.0f);
            float ci0 = c * inv_det;
            float ci1 = -b * inv_det;
            float ci2 = a * inv_det;

            float mid = 0.5f * (a + c);
            float disc = sqrtf(fmaxf(mid*mid - det, 0.1f));
            float ar0 = 3.0f * sqrtf(fmaxf(mid + disc, 0.0f));
            float ar1 = 3.0f * sqrtf(fmaxf(mid - disc, 0.0f));
            areas_out[2*i+0] = valid ? ar0 : 0.0f;
            areas_out[2*i+1] = valid ? ar1 : 0.0f;

            float alpha = __fdividef(1.0f, 1.0f + __expf(-alphas_raw[i]));
            float alpha_eff = valid ? alpha : 0.0f;

            float wx = -1.0f, wy = -1.0f;
            if (valid && alpha_eff >= (1.0f/255.0f)) {
                float tau = 2.0f * __logf(255.0f * alpha_eff);
                if (tau > 0.0f) {
                    wx = sqrtf(tau * a) + 0.05f;
                    wy = sqrtf(tau * c) + 0.05f;
                }
            }

            srec[li*12 + 0] = ux;
            srec[li*12 + 1] = uy;
            srec[li*12 + 2] = -0.5f * L2E * ci0;   // h0
            srec[li*12 + 3] = -L2E * ci1;          // h1
            srec[li*12 + 4] = -0.5f * L2E * ci2;   // h2
            srec[li*12 + 5] = alpha_eff;
            sbb[li] = make_float4(ux, uy, wx, wy);
        }
    }
    __syncthreads();

    // ---------------- Phase 1b: global rank + scatter (2 warps/gaussian) -----
    {
        int w = tid >> 5;
        int lane = tid & 31;
        int pair = w >> 1;                       // local gaussian 0..15
        int half = w & 1;
        int i = blockIdx.x * 16 + pair;
        float d = sd[i];

        int r = 0;
        int j0 = half * 32 + lane;
        #pragma unroll 8
        for (int j = j0; j < NG; j += 64) {      // 32 iters, conflict-free
            float dj = sd[j];
            r += (dj < d) || (dj == d && j < i);
        }
        #pragma unroll
        for (int o = 16; o > 0; o >>= 1) r += __shfl_xor_sync(0xffffffffu, r, o);
        if (lane == 0) prank[w] = r;
        __syncthreads();

        if (half == 0) {
            int rt = prank[2*pair] + prank[2*pair + 1];
            if (lane < 3) {
                g_sorted[rt*3 + lane] = ((const float4*)srec)[pair*3 + lane];
            } else if (lane == 3) {
                g_sbbox[rt] = sbb[pair];
            }
        }
    }

    grid_barrier_tree();

    // ---------------- Phase 2: binning on sorted stream — 2 mirrored tiles ---
    {
        int w = tid >> 5, lane = tid & 31;
        int h = w >> 4;                 // tile half
        int wl = w & 15;
        int tile = h ? (255 - (int)blockIdx.x) : (int)blockIdx.x;
        int tx0 = (tile & 15) * 8;
        int ty0 = (tile >> 4) * 8;
        float bx0 = (float)tx0 + 0.5f, bx1 = (float)tx0 + 7.5f;
        float by0 = (float)ty0 + 0.5f, by1 = (float)ty0 + 7.5f;

        int base0 = wl * (NG / 16);     // 128 sorted gaussians per warp
        float4 bb[4];
        unsigned mk[4];
        #pragma unroll
        for (int u = 0; u < 4; ++u) bb[u] = g_sbbox[base0 + u*32 + lane];
        int cnt = 0;
        #pragma unroll
        for (int u = 0; u < 4; ++u) {
            bool hit = (bb[u].z > 0.0f) &&
                       (bb[u].x - bb[u].z <= bx1) && (bb[u].x + bb[u].z >= bx0) &&
                       (bb[u].y - bb[u].w <= by1) && (bb[u].y + bb[u].w >= by0);
            mk[u] = __ballot_sync(0xffffffffu, hit);
            cnt += __popc(mk[u]);
        }
        if (lane == 0) wcnt[h][wl] = cnt;
        __syncthreads();
        if (tid < 2) {
            int acc = 0;
            #pragma unroll
            for (int w2 = 0; w2 < 16; ++w2) { int t = wcnt[tid][w2]; wcnt[tid][w2] = acc; acc += t; }
            wcnt[tid][16] = acc;
        }
        __syncthreads();
        int off = wcnt[h][wl];
        #pragma unroll
        for (int u = 0; u < 4; ++u) {
            if ((mk[u] >> lane) & 1u) {
                int rank = __popc(mk[u] & ((1u << lane) - 1u));
                sidx[h*NG + off + rank] = base0 + u*32 + lane;   // sorted index
            }
            off += __popc(mk[u]);
        }
        __syncthreads();
    }

    // ---------------- Phase 2.5: gather sorted records into smem (float4) ----
    {
        #pragma unroll
        for (int h2 = 0; h2 < 2; ++h2) {
            int n = min(wcnt[h2][16], CAP);
            const int* ord = sidx + h2*NG;
            float4* dst = (float4*)(rec + h2*CAP*12);
            for (int s = tid; s < n; s += NTHREADS) {
                int gi = ord[s];
                dst[s*3 + 0] = g_sorted[gi*3 + 0];
                dst[s*3 + 1] = g_sorted[gi*3 + 1];
                dst[s*3 + 2] = g_sorted[gi*3 + 2];
            }
        }
        __syncthreads();
    }

    // ---------------- Phase 3: composite — 16 groups, no inner barriers ------
    const int grp = tid >> 6;          // 0..15
    const int h   = grp >> 3;          // tile half
    const int seg = grp & 7;
    const int pix = tid & 63;
    const int tile = h ? (255 - (int)blockIdx.x) : (int)blockIdx.x;
    const int tx0 = (tile & 15) * 8;
    const int ty0 = (tile >> 4) * 8;
    const float px = (float)(tx0 + (pix & 7)) + 0.5f;
    const float py = (float)(ty0 + (pix >> 3)) + 0.5f;

    int n = wcnt[h][16];
    int slen = (n + 7) >> 3;
    int s0 = seg * slen;
    int s1 = min(s0 + slen, n);

    float T = 1.0f;
    float cr = 0.0f, cg = 0.0f, cb = 0.0f;

    const char* rh = (const char*)(rec + h*CAP*12);
    int sm_end = min(s1, CAP);
    for (int j = s0; j < sm_end; ++j) {
        const char* p = rh + j*48;
        float4 A = *(const float4*)(p);          // ux,uy,h0,h1
        float4 B = *(const float4*)(p + 16);     // h2,alpha,r,g
        float  bc = *(const float*)(p + 32);     // b

        float dx = px - A.x;
        float dy = py - A.y;
        float t1 = fmaf(A.w, dy, A.z * dx);
        float q  = fmaf(B.x * dy, dy, dx * t1);  // power * log2(e)
        float e;
        asm("ex2.approx.f32 %0, %1;" : "=f"(e) : "f"(q));
        float g2 = fminf(B.y * e, 0.99f);
        bool ok = (q <= 0.0f) && (g2 >= (1.0f/255.0f));
        float gg = ok ? g2 : 0.0f;
        float w = T * gg;
        cr = fmaf(w, B.z, cr);
        cg = fmaf(w, B.w, cg);
        cb = fmaf(w, bc, cb);
        T -= w;

        if (((j - s0) & 7) == 7 &&
            __all_sync(0xffffffffu, T < 1e-6f)) break;
    }
    // overflow tail (only if tile had > CAP hits): exact, reads global
    if (s1 > CAP && T >= 1e-6f) {
        const int* lst = sidx + h*NG;
        const char* gp = (const char*)g_sorted;
        for (int j = max(s0, CAP); j < s1; ++j) {
            int off = lst[j] * 48;
            float4 A = __ldg((const float4*)(gp + off));
            float4 B = __ldg((const float4*)(gp + off + 16));
            float  bc = __ldg((const float*)(gp + off + 32));
            float dx = px - A.x;
            float dy = py - A.y;
            float t1 = fmaf(A.w, dy, A.z * dx);
            float q  = fmaf(B.x * dy, dy, dx * t1);
            float e;
            asm("ex2.approx.f32 %0, %1;" : "=f"(e) : "f"(q));
            float g2 = fminf(B.y * e, 0.99f);
            bool ok = (q <= 0.0f) && (g2 >= (1.0f/255.0f));
            float gg = ok ? g2 : 0.0f;
            float w = T * gg;
            cr = fmaf(w, B.z, cr);
            cg = fmaf(w, B.w, cg);
            cb = fmaf(w, bc, cb);
            T -= w;
        }
    }

    part[grp*64 + pix] = make_float4(cr, cg, cb, T);
    __syncthreads();

    if (tid < 128) {
        int hh = tid >> 6;             // tile half
        int p2 = tid & 63;
        float4 acc = part[(hh*8 + 0)*64 + p2];
        #pragma unroll
        for (int s2 = 1; s2 < 8; ++s2) {
            float4 qq = part[(hh*8 + s2)*64 + p2];
            acc.x = fmaf(acc.w, qq.x, acc.x);
            acc.y = fmaf(acc.w, qq.y, acc.y);
            acc.z = fmaf(acc.w, qq.z, acc.z);
            acc.w *= qq.w;
        }
        int tl = hh ? (255 - (int)blockIdx.x) : (int)blockIdx.x;
        int x = (tl & 15) * 8 + (p2 & 7);
        int y = (tl >> 4) * 8 + (p2 >> 3);
        out[0*(IMW*IMH) + y*IMW + x] = acc.x;
        out[1*(IMW*IMH) + y*IMW + x] = acc.y;
        out[2*(IMW*IMH) + y*IMW + x] = acc.z;
    }
}

extern "C" void kernel_launch(void* const* d_in, const int* in_sizes, int n_in,
                              void* d_out, int out_size)
{
    const float* pws        = (const float*)d_in[0];
    const float* shs        = (const float*)d_in[1];
    const float* alphas_raw = (const float*)d_in[2];
    const float* scales_raw = (const float*)d_in[3];
    const float* rots_raw   = (const float*)d_in[4];
    // d_in[5] = us (unused by the reference)
    const float* Rcw        = (const float*)d_in[6];
    const float* tcw        = (const float*)d_in[7];

    float* out = (float*)d_out;

    cudaFuncSetAttribute(fused_kernel,
                         cudaFuncAttributeMaxDynamicSharedMemorySize, SMEM_DYN);
    fused_kernel<<<NBLOCKS, NTHREADS, SMEM_DYN>>>(pws, shs, alphas_raw, scales_raw,
                                                  rots_raw, Rcw, tcw, out);
}

// round 14
// speedup vs baseline: 1.0212x; 1.0042x over previous
#include <cuda_runtime.h>
#include <cuda_bf16.h>
#include <math.h>

#define NG 2048
#define IMW 128
#define IMH 128
#define FX 400.0f
#define FY 400.0f
#define CX 64.0f
#define CY 64.0f
#define NBLOCKS 128        // block b owns tiles b and 255-b (mirror pairing)
#define NTHREADS 1024
#define L2E 1.4426950408889634f
#define CAP 1536           // smem record capacity per tile (overflow -> global)

// depth-sorted per-gaussian record (3 float4), exp2-folded conic:
//  [0]ux [1]uy [2]h0 [3]h1 | [4]h2 [5]alpha [6]r [7]g | [8]b [9..11]pad
__device__ float4 g_sorted[NG * 3];
__device__ float4 g_sbbox[NG];         // depth-sorted: ux, uy, wx, wy

__device__ unsigned bar_cnt = 0;
__device__ volatile unsigned bar_gen = 0;

__device__ __forceinline__ void grid_barrier()
{
    __syncthreads();
    if (threadIdx.x == 0) {
        unsigned gen = bar_gen;
        __threadfence();
        unsigned arrived = atomicAdd(&bar_cnt, 1u);
        if (arrived == gridDim.x - 1) {
            bar_cnt = 0;
            __threadfence();
            bar_gen = gen + 1;
        } else {
            while (bar_gen == gen) { }
            __threadfence();
        }
    }
    __syncthreads();
}

__constant__ float kSH_C0 = 0.28209479177387814f;
__constant__ float kSH_C1 = 0.4886025119029199f;

// dynamic smem layout (post-barrier):
//  rec  : float[2][CAP*12]  (147456 B) sorted records staged per tile
//  sidx : int[2][NG]        (16384 B)  binned sorted-stream indices
//  part : float4[16][64]    (16384 B)  segment partials
// pre-barrier aliases (block-local, dead before rec/part are written):
//  sd   : float[NG]  (8 KB, aliases rec)   all-gaussian depths
//  srec : float[16*12] (768 B, after sd)   this block's 16 records
//  sbb  : float4[16]   (256 B, after srec) this block's 16 bboxes
#define OFF_REC  0
#define OFF_SIDX (2*CAP*12*4)
#define OFF_PART (OFF_SIDX + 2*NG*4)
#define SMEM_DYN (OFF_PART + 16*64*16)

__global__ void __launch_bounds__(NTHREADS, 1) fused_kernel(
    const float* __restrict__ pws,
    const float* __restrict__ shs,
    const float* __restrict__ alphas_raw,
    const float* __restrict__ scales_raw,
    const float* __restrict__ rots_raw,
    const float* __restrict__ Rcw,
    const float* __restrict__ tcw,
    float* __restrict__ out)
{
    extern __shared__ char smem_raw[];
    float*  rec  = (float*)(smem_raw + OFF_REC);
    int*    sidx = (int*)(smem_raw + OFF_SIDX);
    float4* part = (float4*)(smem_raw + OFF_PART);
    // pre-barrier aliases
    float*  sd   = (float*)smem_raw;                 // [NG]
    float*  srec = (float*)(smem_raw + NG*4);        // [16*12]
    float4* sbb  = (float4*)(smem_raw + NG*4 + 768); // [16]

    __shared__ int wcnt[2][17];
    __shared__ int prank[16];

    const int tid = threadIdx.x;
    const int wrp = tid >> 5;
    float* areas_out = out + 3 * IMW * IMH;

    // ======== PRE-BARRIER: preprocess (warps 0-1) || depths+rank (warps 2-31)
    if (tid < 64) {
        // ---------------- preprocess 16 gaussians (4 threads each) ----------
        int li = tid >> 2;                  // local gaussian 0..15
        int q  = tid & 3;
        int i  = blockIdx.x * 16 + li;

        float R00 = Rcw[0], R01 = Rcw[1], R02 = Rcw[2];
        float R10 = Rcw[3], R11 = Rcw[4], R12 = Rcw[5];
        float R20 = Rcw[6], R21 = Rcw[7], R22 = Rcw[8];
        float t0 = tcw[0], t1 = tcw[1], t2 = tcw[2];

        float pwx = pws[i*3+0], pwy = pws[i*3+1], pwz = pws[i*3+2];

        if (q < 3) {
            // color lane: channel q
            float twc0 = -(R00*t0 + R10*t1 + R20*t2);
            float twc1 = -(R01*t0 + R11*t1 + R21*t2);
            float twc2 = -(R02*t0 + R12*t1 + R22*t2);
            float dx = pwx - twc0, dy = pwy - twc1, dz = pwz - twc2;
            float dn = rsqrtf(dx*dx + dy*dy + dz*dz);
            float x = dx*dn, y = dy*dn, zd = dz*dn;

            float xx = x*x, yy = y*y, zz = zd*zd;
            float xy = x*y, yz = y*zd, xz = x*zd;

            float bs[16];
            bs[0]  = kSH_C0;
            bs[1]  = -kSH_C1 * y;
            bs[2]  =  kSH_C1 * zd;
            bs[3]  = -kSH_C1 * x;
            bs[4]  =  1.0925484305920792f  * xy;
            bs[5]  = -1.0925484305920792f  * yz;
            bs[6]  =  0.31539156525252005f * (2.0f*zz - xx - yy);
            bs[7]  = -1.0925484305920792f  * xz;
            bs[8]  =  0.5462742152960396f  * (xx - yy);
            bs[9]  = -0.5900435899266435f  * y * (3.0f*xx - yy);
            bs[10] =  2.890611442640554f   * xy * zd;
            bs[11] = -0.4570457994644658f  * y * (4.0f*zz - xx - yy);
            bs[12] =  0.3731763325901154f  * zd * (2.0f*zz - 3.0f*xx - 3.0f*yy);
            bs[13] = -0.4570457994644658f  * x * (4.0f*zz - xx - yy);
            bs[14] =  1.445305721320277f   * zd * (xx - yy);
            bs[15] = -0.5900435899266435f  * x * (xx - 3.0f*yy);

            const float* sh = shs + i*48 + q;
            float v[16];
            #pragma unroll
            for (int j = 0; j < 16; ++j) v[j] = __ldg(sh + j*3);
            float acc = 0.5f;
            #pragma unroll
            for (int j = 0; j < 16; ++j) acc = fmaf(bs[j], v[j], acc);
            srec[li*12 + 6 + q] = fmaxf(acc, 0.0f);
        } else {
            // geometry lane
            float pc0 = R00*pwx + R01*pwy + R02*pwz + t0;
            float pc1 = R10*pwx + R11*pwy + R12*pwz + t1;
            float pc2 = R20*pwx + R21*pwy + R22*pwz + t2;

            float depth = pc2;
            bool valid = depth > 0.2f;
            float z = valid ? depth : 1.0f;
            float invz = __fdividef(1.0f, z);

            float ux = FX * pc0 * invz + CX;
            float uy = FY * pc1 * invz + CY;

            float qw = rots_raw[i*4+0], qx = rots_raw[i*4+1];
            float qy = rots_raw[i*4+2], qz = rots_raw[i*4+3];
            float qn = rsqrtf(qw*qw + qx*qx + qy*qy + qz*qz);
            qw *= qn; qx *= qn; qy *= qn; qz *= qn;

            float r00 = 1.0f - 2.0f*(qy*qy + qz*qz);
            float r01 = 2.0f*(qx*qy - qw*qz);
            float r02 = 2.0f*(qx*qz + qw*qy);
            float r10 = 2.0f*(qx*qy + qw*qz);
            float r11 = 1.0f - 2.0f*(qx*qx + qz*qz);
            float r12 = 2.0f*(qy*qz - qw*qx);
            float r20 = 2.0f*(qx*qz - qw*qy);
            float r21 = 2.0f*(qy*qz + qw*qx);
            float r22 = 1.0f - 2.0f*(qx*qx + qy*qy);

            float s0 = __expf(scales_raw[i*3+0]);
            float s1 = __expf(scales_raw[i*3+1]);
            float s2 = __expf(scales_raw[i*3+2]);

            float m00 = r00*s0, m01 = r01*s1, m02 = r02*s2;
            float m10 = r10*s0, m11 = r11*s1, m12 = r12*s2;
            float m20 = r20*s0, m21 = r21*s1, m22 = r22*s2;

            float Sxx = m00*m00 + m01*m01 + m02*m02;
            float Sxy = m00*m10 + m01*m11 + m02*m12;
            float Sxz = m00*m20 + m01*m21 + m02*m22;
            float Syy = m10*m10 + m11*m11 + m12*m12;
            float Syz = m10*m20 + m11*m21 + m12*m22;
            float Szz = m20*m20 + m21*m21 + m22*m22;

            const float limx = 1.3f * 0.5f * (float)IMW / FX;
            const float limy = 1.3f * 0.5f * (float)IMH / FY;
            float txl = fminf(fmaxf(pc0 * invz, -limx), limx) * z;
            float tyl = fminf(fmaxf(pc1 * invz, -limy), limy) * z;

            float j00 = FX * invz;
            float j02 = -FX * txl * invz * invz;
            float j11 = FY * invz;
            float j12 = -FY * tyl * invz * invz;

            float T00 = j00*R00 + j02*R20;
            float T01 = j00*R01 + j02*R21;
            float T02 = j00*R02 + j02*R22;
            float T10 = j11*R10 + j12*R20;
            float T11 = j11*R11 + j12*R21;
            float T12 = j11*R12 + j12*R22;

            float u0 = T00*Sxx + T01*Sxy + T02*Sxz;
            float u1 = T00*Sxy + T01*Syy + T02*Syz;
            float u2 = T00*Sxz + T01*Syz + T02*Szz;
            float v0 = T10*Sxx + T11*Sxy + T12*Sxz;
            float v1 = T10*Sxy + T11*Syy + T12*Syz;
            float v2 = T10*Sxz + T11*Syz + T12*Szz;

            float a = u0*T00 + u1*T01 + u2*T02 + 0.3f;
            float b = u0*T10 + u1*T11 + u2*T12;
            float c = v0*T10 + v1*T11 + v2*T12 + 0.3f;

            float det = a*c - b*b;
            valid = valid && (det > 0.0f);
            float inv_det = __fdividef(1.0f, valid ? det : 1.0f);
            float ci0 = c * inv_det;
            float ci1 = -b * inv_det;
            float ci2 = a * inv_det;

            float mid = 0.5f * (a + c);
            float disc = sqrtf(fmaxf(mid*mid - det, 0.1f));
            float ar0 = 3.0f * sqrtf(fmaxf(mid + disc, 0.0f));
            float ar1 = 3.0f * sqrtf(fmaxf(mid - disc, 0.0f));
            areas_out[2*i+0] = valid ? ar0 : 0.0f;
            areas_out[2*i+1] = valid ? ar1 : 0.0f;

            float alpha = __fdividef(1.0f, 1.0f + __expf(-alphas_raw[i]));
            float alpha_eff = valid ? alpha : 0.0f;

            float wx = -1.0f, wy = -1.0f;
            if (valid && alpha_eff >= (1.0f/255.0f)) {
                float tau = 2.0f * __logf(255.0f * alpha_eff);
                if (tau > 0.0f) {
                    wx = sqrtf(tau * a) + 0.05f;
                    wy = sqrtf(tau * c) + 0.05f;
                }
            }

            srec[li*12 + 0] = ux;
            srec[li*12 + 1] = uy;
            srec[li*12 + 2] = -0.5f * L2E * ci0;   // h0
            srec[li*12 + 3] = -L2E * ci1;          // h1
            srec[li*12 + 4] = -0.5f * L2E * ci2;   // h2
            srec[li*12 + 5] = alpha_eff;
            sbb[li] = make_float4(ux, uy, wx, wy);
        }
    } else {
        // ---------------- depths (960 threads) then rank (warps 16-31) ------
        float R20 = Rcw[6], R21 = Rcw[7], R22 = Rcw[8];
        float t2 = tcw[2];
        for (int e = tid - 64; e < NG; e += 960) {
            float x = pws[e*3+0], y = pws[e*3+1], z = pws[e*3+2];
            sd[e] = fmaf(R20, x, fmaf(R21, y, fmaf(R22, z, t2)));
        }
        asm volatile("bar.sync 1, 960;" ::: "memory");   // depths ready (warps 2-31)

        if (wrp >= 16) {
            int g = wrp - 16;                  // local gaussian 0..15
            int lane = tid & 31;
            int i = blockIdx.x * 16 + g;
            float d = sd[i];
            int r = 0;
            #pragma unroll 8
            for (int j = lane; j < NG; j += 32) {   // 64 iters, conflict-free
                float dj = sd[j];
                r += (dj < d) || (dj == d && j < i);
            }
            #pragma unroll
            for (int o = 16; o > 0; o >>= 1) r += __shfl_xor_sync(0xffffffffu, r, o);
            if (lane == 0) prank[g] = r;
        }
    }
    __syncthreads();   // srec/sbb/prank all ready

    // ---------------- scatter to global sorted stream (64 threads) -----------
    if (tid < 64) {
        int g = tid >> 2, p = tid & 3;
        int rt = prank[g];
        if (p < 3) {
            g_sorted[rt*3 + p] = ((const float4*)srec)[g*3 + p];
        } else {
            g_sbbox[rt] = sbb[g];
        }
    }

    grid_barrier();

    // ---------------- Phase 2: binning on sorted stream — 2 mirrored tiles ---
    {
        int w = wrp, lane = tid & 31;
        int h = w >> 4;                 // tile half
        int wl = w & 15;
        int tile = h ? (255 - (int)blockIdx.x) : (int)blockIdx.x;
        int tx0 = (tile & 15) * 8;
        int ty0 = (tile >> 4) * 8;
        float bx0 = (float)tx0 + 0.5f, bx1 = (float)tx0 + 7.5f;
        float by0 = (float)ty0 + 0.5f, by1 = (float)ty0 + 7.5f;

        int base0 = wl * (NG / 16);     // 128 sorted gaussians per warp
        float4 bb[4];
        unsigned mk[4];
        #pragma unroll
        for (int u = 0; u < 4; ++u) bb[u] = g_sbbox[base0 + u*32 + lane];
        int cnt = 0;
        #pragma unroll
        for (int u = 0; u < 4; ++u) {
            bool hit = (bb[u].z > 0.0f) &&
                       (bb[u].x - bb[u].z <= bx1) && (bb[u].x + bb[u].z >= bx0) &&
                       (bb[u].y - bb[u].w <= by1) && (bb[u].y + bb[u].w >= by0);
            mk[u] = __ballot_sync(0xffffffffu, hit);
            cnt += __popc(mk[u]);
        }
        if (lane == 0) wcnt[h][wl] = cnt;
        __syncthreads();
        if (tid < 2) {
            int acc = 0;
            #pragma unroll
            for (int w2 = 0; w2 < 16; ++w2) { int t = wcnt[tid][w2]; wcnt[tid][w2] = acc; acc += t; }
            wcnt[tid][16] = acc;
        }
        __syncthreads();
        int off = wcnt[h][wl];
        #pragma unroll
        for (int u = 0; u < 4; ++u) {
            if ((mk[u] >> lane) & 1u) {
                int rank = __popc(mk[u] & ((1u << lane) - 1u));
                sidx[h*NG + off + rank] = base0 + u*32 + lane;   // sorted index
            }
            off += __popc(mk[u]);
        }
        __syncthreads();
    }

    // ---------------- Phase 2.5: gather sorted records into smem (float4) ----
    {
        #pragma unroll
        for (int h2 = 0; h2 < 2; ++h2) {
            int n = min(wcnt[h2][16], CAP);
            const int* ord = sidx + h2*NG;
            float4* dst = (float4*)(rec + h2*CAP*12);
            for (int s = tid; s < n; s += NTHREADS) {
                int gi = ord[s];
                dst[s*3 + 0] = g_sorted[gi*3 + 0];
                dst[s*3 + 1] = g_sorted[gi*3 + 1];
                dst[s*3 + 2] = g_sorted[gi*3 + 2];
            }
        }
        __syncthreads();
    }

    // ---------------- Phase 3: composite — 16 groups, no inner barriers ------
    const int grp = wrp >> 1;          // 0..15 (2-warp groups)
    const int h   = grp >> 3;          // tile half
    const int seg = grp & 7;
    const int pix = tid & 63;
    const int tile = h ? (255 - (int)blockIdx.x) : (int)blockIdx.x;
    const int tx0 = (tile & 15) * 8;
    const int ty0 = (tile >> 4) * 8;
    const float px = (float)(tx0 + (pix & 7)) + 0.5f;
    const float py = (float)(ty0 + (pix >> 3)) + 0.5f;

    int n = wcnt[h][16];
    int slen = (n + 7) >> 3;
    int s0 = seg * slen;
    int s1 = min(s0 + slen, n);

    float T = 1.0f;
    float cr = 0.0f, cg = 0.0f, cb = 0.0f;

    const char* rh = (const char*)(rec + h*CAP*12);
    int sm_end = min(s1, CAP);
    for (int j = s0; j < sm_end; ++j) {
        const char* p = rh + j*48;
        float4 A = *(const float4*)(p);          // ux,uy,h0,h1
        float4 B = *(const float4*)(p + 16);     // h2,alpha,r,g
        float  bc = *(const float*)(p + 32);     // b

        float dx = px - A.x;
        float dy = py - A.y;
        float t1 = fmaf(A.w, dy, A.z * dx);
        float q  = fmaf(B.x * dy, dy, dx * t1);  // power * log2(e)
        float e;
        asm("ex2.approx.f32 %0, %1;" : "=f"(e) : "f"(q));
        float g2 = fminf(B.y * e, 0.99f);
        bool ok = (q <= 0.0f) && (g2 >= (1.0f/255.0f));
        float gg = ok ? g2 : 0.0f;
        float w = T * gg;
        cr = fmaf(w, B.z, cr);
        cg = fmaf(w, B.w, cg);
        cb = fmaf(w, bc, cb);
        T -= w;

        if (((j - s0) & 7) == 7 &&
            __all_sync(0xffffffffu, T < 1e-6f)) break;
    }
    // overflow tail (only if tile had > CAP hits): exact, reads global
    if (s1 > CAP && T >= 1e-6f) {
        const int* lst = sidx + h*NG;
        const char* gp = (const char*)g_sorted;
        for (int j = max(s0, CAP); j < s1; ++j) {
            int off = lst[j] * 48;
            float4 A = __ldg((const float4*)(gp + off));
            float4 B = __ldg((const float4*)(gp + off + 16));
            float  bc = __ldg((const float*)(gp + off + 32));
            float dx = px - A.x;
            float dy = py - A.y;
            float t1 = fmaf(A.w, dy, A.z * dx);
            float q  = fmaf(B.x * dy, dy, dx * t1);
            float e;
            asm("ex2.approx.f32 %0, %1;" : "=f"(e) : "f"(q));
            float g2 = fminf(B.y * e, 0.99f);
            bool ok = (q <= 0.0f) && (g2 >= (1.0f/255.0f));
            float gg = ok ? g2 : 0.0f;
            float w = T * gg;
            cr = fmaf(w, B.z, cr);
            cg = fmaf(w, B.w, cg);
            cb = fmaf(w, bc, cb);
            T -= w;
        }
    }

    part[grp*64 + pix] = make_float4(cr, cg, cb, T);
    __syncthreads();

    if (tid < 128) {
        int hh = tid >> 6;             // tile half
        int p2 = tid & 63;
        float4 acc = part[(hh*8 + 0)*64 + p2];
        #pragma unroll
        for (int s2 = 1; s2 < 8; ++s2) {
            float4 qq = part[(hh*8 + s2)*64 + p2];
            acc.x = fmaf(acc.w, qq.x, acc.x);
            acc.y = fmaf(acc.w, qq.y, acc.y);
            acc.z = fmaf(acc.w, qq.z, acc.z);
            acc.w *= qq.w;
        }
        int tl = hh ? (255 - (int)blockIdx.x) : (int)blockIdx.x;
        int x = (tl & 15) * 8 + (p2 & 7);
        int y = (tl >> 4) * 8 + (p2 >> 3);
        out[0*(IMW*IMH) + y*IMW + x] = acc.x;
        out[1*(IMW*IMH) + y*IMW + x] = acc.y;
        out[2*(IMW*IMH) + y*IMW + x] = acc.z;
    }
}

extern "C" void kernel_launch(void* const* d_in, const int* in_sizes, int n_in,
                              void* d_out, int out_size)
{
    const float* pws        = (const float*)d_in[0];
    const float* shs        = (const float*)d_in[1];
    const float* alphas_raw = (const float*)d_in[2];
    const float* scales_raw = (const float*)d_in[3];
    const float* rots_raw   = (const float*)d_in[4];
    // d_in[5] = us (unused by the reference)
    const float* Rcw        = (const float*)d_in[6];
    const float* tcw        = (const float*)d_in[7];

    float* out = (float*)d_out;

    cudaFuncSetAttribute(fused_kernel,
                         cudaFuncAttributeMaxDynamicSharedMemorySize, SMEM_DYN);
    fused_kernel<<<NBLOCKS, NTHREADS, SMEM_DYN>>>(pws, shs, alphas_raw, scales_raw,
                                                  rots_raw, Rcw, tcw, out);
}

// round 15
// speedup vs baseline: 1.0548x; 1.0329x over previous
#include <cuda_runtime.h>
#include <cuda_bf16.h>
#include <math.h>

#define NG 2048
#define IMW 128
#define IMH 128
#define FX 400.0f
#define FY 400.0f
#define CX 64.0f
#define CY 64.0f
#define NBLOCKS 128        // block b owns tiles b and 255-b (mirror pairing)
#define NTHREADS 1024
#define L2E 1.4426950408889634f
#define CAP 1536           // smem record capacity per tile (overflow -> global)

// depth-sorted per-gaussian record (3 float4), exp2-folded conic:
//  [0]ux [1]uy [2]h0 [3]h1 | [4]h2 [5]alpha [6]r [7]g | [8]b [9..11]pad
__device__ float4 g_sorted[NG * 3];
__device__ float4 g_sbbox[NG];         // depth-sorted: ux, uy, wx, wy

__device__ unsigned bar_cnt = 0;
__device__ volatile unsigned bar_gen = 0;

__device__ __forceinline__ void grid_barrier()
{
    __syncthreads();
    if (threadIdx.x == 0) {
        unsigned gen = bar_gen;
        __threadfence();
        unsigned arrived = atomicAdd(&bar_cnt, 1u);
        if (arrived == gridDim.x - 1) {
            bar_cnt = 0;
            __threadfence();
            bar_gen = gen + 1;
        } else {
            while (bar_gen == gen) __nanosleep(32);
            __threadfence();
        }
    }
    __syncthreads();
}

__constant__ float kSH_C0 = 0.28209479177387814f;
__constant__ float kSH_C1 = 0.4886025119029199f;

// dynamic smem layout (post-barrier):
//  rec  : float[2][CAP*12]  (147456 B) sorted records staged per tile
//  sidx : int[2][NG]        (16384 B)  binned sorted-stream indices
//  part : float4[16][64]    (16384 B)  segment partials
// pre-barrier aliases (block-local, dead before rec/part are written):
//  sd   : float[NG]  (8 KB, aliases rec)   all-gaussian depths
//  srec : float[16*12] (768 B, after sd)   this block's 16 records
//  sbb  : float4[16]   (256 B, after srec) this block's 16 bboxes
#define OFF_REC  0
#define OFF_SIDX (2*CAP*12*4)
#define OFF_PART (OFF_SIDX + 2*NG*4)
#define SMEM_DYN (OFF_PART + 16*64*16)

__global__ void __launch_bounds__(NTHREADS, 1) fused_kernel(
    const float* __restrict__ pws,
    const float* __restrict__ shs,
    const float* __restrict__ alphas_raw,
    const float* __restrict__ scales_raw,
    const float* __restrict__ rots_raw,
    const float* __restrict__ Rcw,
    const float* __restrict__ tcw,
    float* __restrict__ out)
{
    extern __shared__ char smem_raw[];
    float*  rec  = (float*)(smem_raw + OFF_REC);
    int*    sidx = (int*)(smem_raw + OFF_SIDX);
    float4* part = (float4*)(smem_raw + OFF_PART);
    // pre-barrier aliases
    float*  sd   = (float*)smem_raw;                 // [NG]
    float*  srec = (float*)(smem_raw + NG*4);        // [16*12]
    float4* sbb  = (float4*)(smem_raw + NG*4 + 768); // [16]

    __shared__ int wcnt[2][17];
    __shared__ int prank[16];

    const int tid = threadIdx.x;
    const int wrp = tid >> 5;
    float* areas_out = out + 3 * IMW * IMH;

    // ======== PRE-BARRIER: preprocess (warps 0-1) || depths+rank (warps 2-31)
    if (tid < 64) {
        // ---------------- preprocess 16 gaussians (4 threads each) ----------
        int li = tid >> 2;                  // local gaussian 0..15
        int q  = tid & 3;
        int i  = blockIdx.x * 16 + li;

        float R00 = Rcw[0], R01 = Rcw[1], R02 = Rcw[2];
        float R10 = Rcw[3], R11 = Rcw[4], R12 = Rcw[5];
        float R20 = Rcw[6], R21 = Rcw[7], R22 = Rcw[8];
        float t0 = tcw[0], t1 = tcw[1], t2 = tcw[2];

        float pwx = pws[i*3+0], pwy = pws[i*3+1], pwz = pws[i*3+2];

        if (q < 3) {
            // color lane: channel q
            float twc0 = -(R00*t0 + R10*t1 + R20*t2);
            float twc1 = -(R01*t0 + R11*t1 + R21*t2);
            float twc2 = -(R02*t0 + R12*t1 + R22*t2);
            float dx = pwx - twc0, dy = pwy - twc1, dz = pwz - twc2;
            float dn = rsqrtf(dx*dx + dy*dy + dz*dz);
            float x = dx*dn, y = dy*dn, zd = dz*dn;

            float xx = x*x, yy = y*y, zz = zd*zd;
            float xy = x*y, yz = y*zd, xz = x*zd;

            float bs[16];
            bs[0]  = kSH_C0;
            bs[1]  = -kSH_C1 * y;
            bs[2]  =  kSH_C1 * zd;
            bs[3]  = -kSH_C1 * x;
            bs[4]  =  1.0925484305920792f  * xy;
            bs[5]  = -1.0925484305920792f  * yz;
            bs[6]  =  0.31539156525252005f * (2.0f*zz - xx - yy);
            bs[7]  = -1.0925484305920792f  * xz;
            bs[8]  =  0.5462742152960396f  * (xx - yy);
            bs[9]  = -0.5900435899266435f  * y * (3.0f*xx - yy);
            bs[10] =  2.890611442640554f   * xy * zd;
            bs[11] = -0.4570457994644658f  * y * (4.0f*zz - xx - yy);
            bs[12] =  0.3731763325901154f  * zd * (2.0f*zz - 3.0f*xx - 3.0f*yy);
            bs[13] = -0.4570457994644658f  * x * (4.0f*zz - xx - yy);
            bs[14] =  1.445305721320277f   * zd * (xx - yy);
            bs[15] = -0.5900435899266435f  * x * (xx - 3.0f*yy);

            const float* sh = shs + i*48 + q;
            float v[16];
            #pragma unroll
            for (int j = 0; j < 16; ++j) v[j] = __ldg(sh + j*3);
            float acc = 0.5f;
            #pragma unroll
            for (int j = 0; j < 16; ++j) acc = fmaf(bs[j], v[j], acc);
            srec[li*12 + 6 + q] = fmaxf(acc, 0.0f);
        } else {
            // geometry lane
            float pc0 = R00*pwx + R01*pwy + R02*pwz + t0;
            float pc1 = R10*pwx + R11*pwy + R12*pwz + t1;
            float pc2 = R20*pwx + R21*pwy + R22*pwz + t2;

            float depth = pc2;
            bool valid = depth > 0.2f;
            float z = valid ? depth : 1.0f;
            float invz = __fdividef(1.0f, z);

            float ux = FX * pc0 * invz + CX;
            float uy = FY * pc1 * invz + CY;

            float qw = rots_raw[i*4+0], qx = rots_raw[i*4+1];
            float qy = rots_raw[i*4+2], qz = rots_raw[i*4+3];
            float qn = rsqrtf(qw*qw + qx*qx + qy*qy + qz*qz);
            qw *= qn; qx *= qn; qy *= qn; qz *= qn;

            float r00 = 1.0f - 2.0f*(qy*qy + qz*qz);
            float r01 = 2.0f*(qx*qy - qw*qz);
            float r02 = 2.0f*(qx*qz + qw*qy);
            float r10 = 2.0f*(qx*qy + qw*qz);
            float r11 = 1.0f - 2.0f*(qx*qx + qz*qz);
            float r12 = 2.0f*(qy*qz - qw*qx);
            float r20 = 2.0f*(qx*qz - qw*qy);
            float r21 = 2.0f*(qy*qz + qw*qx);
            float r22 = 1.0f - 2.0f*(qx*qx + qy*qy);

            float s0 = __expf(scales_raw[i*3+0]);
            float s1 = __expf(scales_raw[i*3+1]);
            float s2 = __expf(scales_raw[i*3+2]);

            float m00 = r00*s0, m01 = r01*s1, m02 = r02*s2;
            float m10 = r10*s0, m11 = r11*s1, m12 = r12*s2;
            float m20 = r20*s0, m21 = r21*s1, m22 = r22*s2;

            float Sxx = m00*m00 + m01*m01 + m02*m02;
            float Sxy = m00*m10 + m01*m11 + m02*m12;
            float Sxz = m00*m20 + m01*m21 + m02*m22;
            float Syy = m10*m10 + m11*m11 + m12*m12;
            float Syz = m10*m20 + m11*m21 + m12*m22;
            float Szz = m20*m20 + m21*m21 + m22*m22;

            const float limx = 1.3f * 0.5f * (float)IMW / FX;
            const float limy = 1.3f * 0.5f * (float)IMH / FY;
            float txl = fminf(fmaxf(pc0 * invz, -limx), limx) * z;
            float tyl = fminf(fmaxf(pc1 * invz, -limy), limy) * z;

            float j00 = FX * invz;
            float j02 = -FX * txl * invz * invz;
            float j11 = FY * invz;
            float j12 = -FY * tyl * invz * invz;

            float T00 = j00*R00 + j02*R20;
            float T01 = j00*R01 + j02*R21;
            float T02 = j00*R02 + j02*R22;
            float T10 = j11*R10 + j12*R20;
            float T11 = j11*R11 + j12*R21;
            float T12 = j11*R12 + j12*R22;

            float u0 = T00*Sxx + T01*Sxy + T02*Sxz;
            float u1 = T00*Sxy + T01*Syy + T02*Syz;
            float u2 = T00*Sxz + T01*Syz + T02*Szz;
            float v0 = T10*Sxx + T11*Sxy + T12*Sxz;
            float v1 = T10*Sxy + T11*Syy + T12*Syz;
            float v2 = T10*Sxz + T11*Syz + T12*Szz;

            float a = u0*T00 + u1*T01 + u2*T02 + 0.3f;
            float b = u0*T10 + u1*T11 + u2*T12;
            float c = v0*T10 + v1*T11 + v2*T12 + 0.3f;

            float det = a*c - b*b;
            valid = valid && (det > 0.0f);
            float inv_det = __fdividef(1.0f, valid ? det : 1.0f);
            float ci0 = c * inv_det;
            float ci1 = -b * inv_det;
            float ci2 = a * inv_det;

            float mid = 0.5f * (a + c);
            float disc = sqrtf(fmaxf(mid*mid - det, 0.1f));
            float ar0 = 3.0f * sqrtf(fmaxf(mid + disc, 0.0f));
            float ar1 = 3.0f * sqrtf(fmaxf(mid - disc, 0.0f));
            areas_out[2*i+0] = valid ? ar0 : 0.0f;
            areas_out[2*i+1] = valid ? ar1 : 0.0f;

            float alpha = __fdividef(1.0f, 1.0f + __expf(-alphas_raw[i]));
            float alpha_eff = valid ? alpha : 0.0f;

            float wx = -1.0f, wy = -1.0f;
            if (valid && alpha_eff >= (1.0f/255.0f)) {
                float tau = 2.0f * __logf(255.0f * alpha_eff);
                if (tau > 0.0f) {
                    wx = sqrtf(tau * a) + 0.05f;
                    wy = sqrtf(tau * c) + 0.05f;
                }
            }

            srec[li*12 + 0] = ux;
            srec[li*12 + 1] = uy;
            srec[li*12 + 2] = -0.5f * L2E * ci0;   // h0
            srec[li*12 + 3] = -L2E * ci1;          // h1
            srec[li*12 + 4] = -0.5f * L2E * ci2;   // h2
            srec[li*12 + 5] = alpha_eff;
            sbb[li] = make_float4(ux, uy, wx, wy);
        }
    } else {
        // ---------------- depths (960 threads) then rank (warps 16-31) ------
        float R20 = Rcw[6], R21 = Rcw[7], R22 = Rcw[8];
        float t2 = tcw[2];
        for (int e = tid - 64; e < NG; e += 960) {
            float x = pws[e*3+0], y = pws[e*3+1], z = pws[e*3+2];
            sd[e] = fmaf(R20, x, fmaf(R21, y, fmaf(R22, z, t2)));
        }
        asm volatile("bar.sync 1, 960;" ::: "memory");   // depths ready (warps 2-31)

        if (wrp >= 16) {
            int g = wrp - 16;                  // local gaussian 0..15
            int lane = tid & 31;
            int i = blockIdx.x * 16 + g;
            float d = sd[i];
            int r = 0;
            #pragma unroll 8
            for (int j = lane; j < NG; j += 32) {   // 64 iters, conflict-free
                float dj = sd[j];
                r += (dj < d) || (dj == d && j < i);
            }
            #pragma unroll
            for (int o = 16; o > 0; o >>= 1) r += __shfl_xor_sync(0xffffffffu, r, o);
            if (lane == 0) prank[g] = r;
        }
    }
    __syncthreads();   // srec/sbb/prank all ready

    // ---------------- scatter to global sorted stream (64 threads) -----------
    if (tid < 64) {
        int g = tid >> 2, p = tid & 3;
        int rt = prank[g];
        if (p < 3) {
            g_sorted[rt*3 + p] = ((const float4*)srec)[g*3 + p];
        } else {
            g_sbbox[rt] = sbb[g];
        }
    }

    grid_barrier();

    // ---------------- Phase 2: binning on sorted stream — 2 mirrored tiles ---
    {
        int w = wrp, lane = tid & 31;
        int h = w >> 4;                 // tile half
        int wl = w & 15;
        int tile = h ? (255 - (int)blockIdx.x) : (int)blockIdx.x;
        int tx0 = (tile & 15) * 8;
        int ty0 = (tile >> 4) * 8;
        float bx0 = (float)tx0 + 0.5f, bx1 = (float)tx0 + 7.5f;
        float by0 = (float)ty0 + 0.5f, by1 = (float)ty0 + 7.5f;

        int base0 = wl * (NG / 16);     // 128 sorted gaussians per warp
        float4 bb[4];
        unsigned mk[4];
        #pragma unroll
        for (int u = 0; u < 4; ++u) bb[u] = g_sbbox[base0 + u*32 + lane];
        int cnt = 0;
        #pragma unroll
        for (int u = 0; u < 4; ++u) {
            bool hit = (bb[u].z > 0.0f) &&
                       (bb[u].x - bb[u].z <= bx1) && (bb[u].x + bb[u].z >= bx0) &&
                       (bb[u].y - bb[u].w <= by1) && (bb[u].y + bb[u].w >= by0);
            mk[u] = __ballot_sync(0xffffffffu, hit);
            cnt += __popc(mk[u]);
        }
        if (lane == 0) wcnt[h][wl] = cnt;
        __syncthreads();
        if (tid < 2) {
            int acc = 0;
            #pragma unroll
            for (int w2 = 0; w2 < 16; ++w2) { int t = wcnt[tid][w2]; wcnt[tid][w2] = acc; acc += t; }
            wcnt[tid][16] = acc;
        }
        __syncthreads();
        int off = wcnt[h][wl];
        #pragma unroll
        for (int u = 0; u < 4; ++u) {
            if ((mk[u] >> lane) & 1u) {
                int rank = __popc(mk[u] & ((1u << lane) - 1u));
                sidx[h*NG + off + rank] = base0 + u*32 + lane;   // sorted index
            }
            off += __popc(mk[u]);
        }
        __syncthreads();
    }

    // ---------------- Phase 2.5: gather sorted records into smem (float4) ----
    {
        #pragma unroll
        for (int h2 = 0; h2 < 2; ++h2) {
            int n = min(wcnt[h2][16], CAP);
            const int* ord = sidx + h2*NG;
            float4* dst = (float4*)(rec + h2*CAP*12);
            for (int s = tid; s < n; s += NTHREADS) {
                int gi = ord[s];
                dst[s*3 + 0] = g_sorted[gi*3 + 0];
                dst[s*3 + 1] = g_sorted[gi*3 + 1];
                dst[s*3 + 2] = g_sorted[gi*3 + 2];
            }
        }
        __syncthreads();
    }

    // ---------------- Phase 3: composite — 16 groups, no inner barriers ------
    const int grp = wrp >> 1;          // 0..15 (2-warp groups)
    const int h   = grp >> 3;          // tile half
    const int seg = grp & 7;
    const int pix = tid & 63;
    const int tile = h ? (255 - (int)blockIdx.x) : (int)blockIdx.x;
    const int tx0 = (tile & 15) * 8;
    const int ty0 = (tile >> 4) * 8;
    const float px = (float)(tx0 + (pix & 7)) + 0.5f;
    const float py = (float)(ty0 + (pix >> 3)) + 0.5f;

    int n = wcnt[h][16];
    int slen = (n + 7) >> 3;
    int s0 = seg * slen;
    int s1 = min(s0 + slen, n);

    float T = 1.0f;
    float cr = 0.0f, cg = 0.0f, cb = 0.0f;

    const char* rh = (const char*)(rec + h*CAP*12);
    int sm_end = min(s1, CAP);
    for (int j = s0; j < sm_end; ++j) {
        const char* p = rh + j*48;
        float4 A = *(const float4*)(p);          // ux,uy,h0,h1
        float4 B = *(const float4*)(p + 16);     // h2,alpha,r,g
        float  bc = *(const float*)(p + 32);     // b

        float dx = px - A.x;
        float dy = py - A.y;
        float t1 = fmaf(A.w, dy, A.z * dx);
        float q  = fmaf(B.x * dy, dy, dx * t1);  // power * log2(e)
        float e;
        asm("ex2.approx.f32 %0, %1;" : "=f"(e) : "f"(q));
        float g2 = fminf(B.y * e, 0.99f);
        bool ok = (q <= 0.0f) && (g2 >= (1.0f/255.0f));
        float gg = ok ? g2 : 0.0f;
        float w = T * gg;
        cr = fmaf(w, B.z, cr);
        cg = fmaf(w, B.w, cg);
        cb = fmaf(w, bc, cb);
        T -= w;

        if (((j - s0) & 15) == 15 &&
            __all_sync(0xffffffffu, T < 1e-6f)) break;
    }
    // overflow tail (only if tile had > CAP hits): exact, reads global
    if (s1 > CAP && T >= 1e-6f) {
        const int* lst = sidx + h*NG;
        const char* gp = (const char*)g_sorted;
        for (int j = max(s0, CAP); j < s1; ++j) {
            int off = lst[j] * 48;
            float4 A = __ldg((const float4*)(gp + off));
            float4 B = __ldg((const float4*)(gp + off + 16));
            float  bc = __ldg((const float*)(gp + off + 32));
            float dx = px - A.x;
            float dy = py - A.y;
            float t1 = fmaf(A.w, dy, A.z * dx);
            float q  = fmaf(B.x * dy, dy, dx * t1);
            float e;
            asm("ex2.approx.f32 %0, %1;" : "=f"(e) : "f"(q));
            float g2 = fminf(B.y * e, 0.99f);
            bool ok = (q <= 0.0f) && (g2 >= (1.0f/255.0f));
            float gg = ok ? g2 : 0.0f;
            float w = T * gg;
            cr = fmaf(w, B.z, cr);
            cg = fmaf(w, B.w, cg);
            cb = fmaf(w, bc, cb);
            T -= w;
        }
    }

    part[grp*64 + pix] = make_float4(cr, cg, cb, T);
    __syncthreads();

    if (tid < 128) {
        int hh = tid >> 6;             // tile half
        int p2 = tid & 63;
        float4 acc = part[(hh*8 + 0)*64 + p2];
        #pragma unroll
        for (int s2 = 1; s2 < 8; ++s2) {
            float4 qq = part[(hh*8 + s2)*64 + p2];
            acc.x = fmaf(acc.w, qq.x, acc.x);
            acc.y = fmaf(acc.w, qq.y, acc.y);
            acc.z = fmaf(acc.w, qq.z, acc.z);
            acc.w *= qq.w;
        }
        int tl = hh ? (255 - (int)blockIdx.x) : (int)blockIdx.x;
        int x = (tl & 15) * 8 + (p2 & 7);
        int y = (tl >> 4) * 8 + (p2 >> 3);
        out[0*(IMW*IMH) + y*IMW + x] = acc.x;
        out[1*(IMW*IMH) + y*IMW + x] = acc.y;
        out[2*(IMW*IMH) + y*IMW + x] = acc.z;
    }
}

extern "C" void kernel_launch(void* const* d_in, const int* in_sizes, int n_in,
                              void* d_out, int out_size)
{
    const float* pws        = (const float*)d_in[0];
    const float* shs        = (const float*)d_in[1];
    const float* alphas_raw = (const float*)d_in[2];
    const float* scales_raw = (const float*)d_in[3];
    const float* rots_raw   = (const float*)d_in[4];
    // d_in[5] = us (unused by the reference)
    const float* Rcw        = (const float*)d_in[6];
    const float* tcw        = (const float*)d_in[7];

    float* out = (float*)d_out;

    cudaFuncSetAttribute(fused_kernel,
                         cudaFuncAttributeMaxDynamicSharedMemorySize, SMEM_DYN);
    fused_kernel<<<NBLOCKS, NTHREADS, SMEM_DYN>>>(pws, shs, alphas_raw, scales_raw,
                                                  rots_raw, Rcw, tcw, out);
}